// round 6
// baseline (speedup 1.0000x reference)
#include <cuda_runtime.h>
#include <cstdint>

// SigmaModel, persistent-CTA version.
// h = relu([s,a] @ W1^T + b1); tri = h @ W2^T + b2;
// out[b,i,j] = tri[t(min(i,j),max(i,j))], diag -> exp.
// 152 persistent CTAs; W2 staged in smem ONCE; grid-stride over 2048 row-tiles.

#define BATCH    131072
#define SDIM     32
#define ADIM     8
#define INDIM    40
#define HID      64
#define TRI      528
#define ROWS     64          // rows per tile
#define NT       512
#define GRID     152         // GB300 SM count
#define NTILES   (BATCH / ROWS)   // 2048
#define NPAD     580         // W2 k-major stride (mult of 4 -> LDS.128 aligned)
#define HPAD     65          // H stride (banked row groups)
#define XPAD     40          // X stride (160B rows -> 16B-aligned cp.async)

// shared memory layout (float offsets)
#define SM_W2    0           // [64][NPAD] = 37120 floats, persists across tiles
#define SM_H     37120       // [64][HPAD] = 4160
#define SM_X     41280       // [64][XPAD] = 2560
#define SM_W1    43840       // [40][64] transposed = 2560
#define SM_B1    46400       // [64]
#define SM_B2    46464       // [576], pad zeros
#define SM_OT    47040       // u32[576]: o1 | o2<<10 | diag<<20 | invalid<<31
#define SM_FLOATS 47616      // 190464 bytes

typedef unsigned long long u64;

__device__ __forceinline__ u64 pack2(float lo, float hi) {
    u64 r; asm("mov.b64 %0, {%1, %2};" : "=l"(r) : "f"(lo), "f"(hi)); return r;
}
__device__ __forceinline__ void unpack2(u64 v, float& lo, float& hi) {
    asm("mov.b64 {%0, %1}, %2;" : "=f"(lo), "=f"(hi) : "l"(v));
}
__device__ __forceinline__ void fma2(u64& d, u64 a, u64 b) {
    asm("fma.rn.f32x2 %0, %1, %2, %0;" : "+l"(d) : "l"(a), "l"(b));
}
__device__ __forceinline__ uint32_t smem_u32(const void* p) {
    uint32_t r;
    asm("{ .reg .u64 t; cvta.to.shared.u64 t, %1; cvt.u32.u64 %0, t; }" : "=r"(r) : "l"(p));
    return r;
}
__device__ __forceinline__ void cp16(uint32_t dst, const void* src) {
    asm volatile("cp.async.ca.shared.global [%0], [%1], 16;" :: "r"(dst), "l"(src));
}
__device__ __forceinline__ void cp_commit() {
    asm volatile("cp.async.commit_group;" ::: "memory");
}
__device__ __forceinline__ void cp_wait0() {
    asm volatile("cp.async.wait_group 0;" ::: "memory");
}

__global__ void __launch_bounds__(NT, 1)
sigma_persist_kernel(const float* __restrict__ s,
                     const float* __restrict__ a,
                     const float* __restrict__ W1,
                     const float* __restrict__ b1,
                     const float* __restrict__ W2,
                     const float* __restrict__ b2,
                     float* __restrict__ out) {
    extern __shared__ float smem[];
    float* sW2 = smem + SM_W2;
    float* sH  = smem + SM_H;
    float* sX  = smem + SM_X;
    float* sW1 = smem + SM_W1;
    float* sB1 = smem + SM_B1;
    float* sB2 = smem + SM_B2;
    uint32_t* sOT = (uint32_t*)(smem + SM_OT);

    const int tid = threadIdx.x;
    const uint32_t sXaddr = smem_u32(sX);

    // ================= one-time staging =================
    // W2[t][k] -> sW2[k][t], LDG.128 along k, 4x STS.32 transpose
    for (int idx = tid; idx < TRI * (HID / 4); idx += NT) {
        int t = idx >> 4, k4 = idx & 15;
        float4 w = *reinterpret_cast<const float4*>(&W2[t * HID + k4 * 4]);
        sW2[(4 * k4 + 0) * NPAD + t] = w.x;
        sW2[(4 * k4 + 1) * NPAD + t] = w.y;
        sW2[(4 * k4 + 2) * NPAD + t] = w.z;
        sW2[(4 * k4 + 3) * NPAD + t] = w.w;
    }
    // zero-pad W2 cols [TRI, NPAD)
    for (int idx = tid; idx < HID * (NPAD - TRI); idx += NT) {
        int k = idx / (NPAD - TRI), t = TRI + (idx - k * (NPAD - TRI));
        sW2[k * NPAD + t] = 0.0f;
    }
    // W1[hh][k] -> sW1[k][hh]
    for (int idx = tid; idx < HID * INDIM; idx += NT) {
        int hh = idx / INDIM, k = idx - hh * INDIM;
        sW1[k * HID + hh] = W1[idx];
    }
    if (tid < HID) sB1[tid] = b1[tid];
    for (int idx = tid; idx < 576; idx += NT)
        sB2[idx] = (idx < TRI) ? b2[idx] : 0.0f;
    // out-offset table: tri col t -> (upper o1, mirror o2, diag)
    for (int idx = tid; idx < 1024; idx += NT) {
        int i = idx >> 5, j = idx & 31;
        if (j >= i) {
            int t = 32 * i - ((i * (i + 1)) >> 1) + j;
            sOT[t] = (uint32_t)(i * 32 + j) | ((uint32_t)(j * 32 + i) << 10) |
                     ((i == j) ? (1u << 20) : 0u);
        }
    }
    for (int idx = tid; idx < NPAD - TRI; idx += NT)
        if (TRI + idx < 576) sOT[TRI + idx] = 0x80000000u;

    // prefetch X for first tile
    const int tile0 = blockIdx.x;
    {
        int row0 = tile0 * ROWS;
        int r = tid >> 3, c4 = tid & 7;
        cp16(sXaddr + (r * XPAD + c4 * 4) * 4, &s[(size_t)(row0 + r) * SDIM + c4 * 4]);
        if (tid < 128) {
            int r2 = tid >> 1, d4 = tid & 1;
            cp16(sXaddr + (r2 * XPAD + SDIM + d4 * 4) * 4,
                 &a[(size_t)(row0 + r2) * ADIM + d4 * 4]);
        }
        cp_commit();
    }
    cp_wait0();
    __syncthreads();

    // GEMM thread mapping (constant across tiles)
    const int wi   = tid >> 5, lane = tid & 31;
    const int rb   = wi >> 3,  cb   = wi & 7;     // 2 row-blocks x 8 col-blocks
    const int rg   = lane & 7, cg   = lane >> 3;  // 8 row-groups x 4 col-groups
    const int wcol = cb * 72;

    // ================= persistent tile loop =================
    for (int tile = tile0; tile < NTILES; tile += GRID) {
        const int row0 = tile * ROWS;

        // ---- Phase 1: H = relu(X @ W1^T + b1) ----
        {
            const int r  = tid >> 3;
            const int hg = (tid & 7) * 8;
            u64 acc[4];
#pragma unroll
            for (int u = 0; u < 4; ++u)
                acc[u] = *reinterpret_cast<const u64*>(&sB1[hg + 2 * u]);
            const float* xrow = &sX[r * XPAD];
#pragma unroll 5
            for (int k = 0; k < INDIM; ++k) {
                u64 xb = pack2(xrow[k], xrow[k]);
                const ulonglong2 w0 = *reinterpret_cast<const ulonglong2*>(&sW1[k * HID + hg]);
                const ulonglong2 w1 = *reinterpret_cast<const ulonglong2*>(&sW1[k * HID + hg + 4]);
                fma2(acc[0], xb, w0.x); fma2(acc[1], xb, w0.y);
                fma2(acc[2], xb, w1.x); fma2(acc[3], xb, w1.y);
            }
            float* hrow = &sH[r * HPAD + hg];
#pragma unroll
            for (int u = 0; u < 4; ++u) {
                float lo, hi; unpack2(acc[u], lo, hi);
                hrow[2 * u]     = fmaxf(lo, 0.0f);
                hrow[2 * u + 1] = fmaxf(hi, 0.0f);
            }
        }
        __syncthreads();   // sH ready; sX free for prefetch

        // ---- prefetch X of next tile (hidden under GEMM) ----
        if (tile + GRID < NTILES) {
            int nrow0 = (tile + GRID) * ROWS;
            int r = tid >> 3, c4 = tid & 7;
            cp16(sXaddr + (r * XPAD + c4 * 4) * 4, &s[(size_t)(nrow0 + r) * SDIM + c4 * 4]);
            if (tid < 128) {
                int r2 = tid >> 1, d4 = tid & 1;
                cp16(sXaddr + (r2 * XPAD + SDIM + d4 * 4) * 4,
                     &a[(size_t)(nrow0 + r2) * ADIM + d4 * 4]);
            }
            cp_commit();
        }

        // ---- Phase 2: tri = H @ W2^T + b2 ----
        u64 acc2[4][9];
#pragma unroll
        for (int q = 0; q < 4; ++q) {
            u64 blo = *reinterpret_cast<const u64*>(&sB2[wcol + 16 * q + 4 * cg]);
            u64 bhi = *reinterpret_cast<const u64*>(&sB2[wcol + 16 * q + 4 * cg + 2]);
#pragma unroll
            for (int m = 0; m < 4; ++m) { acc2[m][2 * q] = blo; acc2[m][2 * q + 1] = bhi; }
        }
        {
            u64 bt = *reinterpret_cast<const u64*>(&sB2[wcol + 64 + 2 * cg]);
#pragma unroll
            for (int m = 0; m < 4; ++m) acc2[m][8] = bt;
        }

        const float* hbase = &sH[(rb * 32 + rg) * HPAD];
#pragma unroll 1
        for (int k = 0; k < HID; ++k) {
            const float* wr = &sW2[k * NPAD + wcol];
            const ulonglong2 q0 = *reinterpret_cast<const ulonglong2*>(wr + 4 * cg);
            const ulonglong2 q1 = *reinterpret_cast<const ulonglong2*>(wr + 16 + 4 * cg);
            const ulonglong2 q2 = *reinterpret_cast<const ulonglong2*>(wr + 32 + 4 * cg);
            const ulonglong2 q3 = *reinterpret_cast<const ulonglong2*>(wr + 48 + 4 * cg);
            const u64 qt = *reinterpret_cast<const u64*>(wr + 64 + 2 * cg);
            u64 hb[4];
#pragma unroll
            for (int m = 0; m < 4; ++m) {
                float hv = hbase[m * 8 * HPAD + k];
                hb[m] = pack2(hv, hv);
            }
#pragma unroll
            for (int m = 0; m < 4; ++m) {
                fma2(acc2[m][0], hb[m], q0.x);
                fma2(acc2[m][1], hb[m], q0.y);
                fma2(acc2[m][2], hb[m], q1.x);
                fma2(acc2[m][3], hb[m], q1.y);
                fma2(acc2[m][4], hb[m], q2.x);
                fma2(acc2[m][5], hb[m], q2.y);
                fma2(acc2[m][6], hb[m], q3.x);
                fma2(acc2[m][7], hb[m], q3.y);
                fma2(acc2[m][8], hb[m], qt);
            }
        }

        // ---- Phase 3: direct scatter-store from accumulators ----
        {
            const int baseRow = row0 + rb * 32 + rg;
#pragma unroll
            for (int u = 0; u < 9; ++u) {
                const int c = (u < 8) ? (wcol + 16 * (u >> 1) + 4 * cg + 2 * (u & 1))
                                      : (wcol + 64 + 2 * cg);
                const uint32_t e0 = sOT[c];
                const uint32_t e1 = sOT[c + 1];
#pragma unroll
                for (int m = 0; m < 4; ++m) {
                    float lo, hi; unpack2(acc2[m][u], lo, hi);
                    float* orow = out + (size_t)(baseRow + 8 * m) * 1024;
                    if (!(e0 >> 31)) {
                        float v = (e0 & (1u << 20)) ? __expf(lo) : lo;
                        orow[e0 & 1023] = v;
                        orow[(e0 >> 10) & 1023] = v;
                    }
                    if (!(e1 >> 31)) {
                        float v = (e1 & (1u << 20)) ? __expf(hi) : hi;
                        orow[e1 & 1023] = v;
                        orow[(e1 >> 10) & 1023] = v;
                    }
                }
            }
        }

        cp_wait0();
        __syncthreads();   // sX(t+1) ready; all GEMM reads of sH done
    }
}

extern "C" void kernel_launch(void* const* d_in, const int* in_sizes, int n_in,
                              void* d_out, int out_size) {
    (void)in_sizes; (void)n_in; (void)out_size;
    const float* s  = (const float*)d_in[0];
    const float* a  = (const float*)d_in[1];
    const float* W1 = (const float*)d_in[2];
    const float* b1 = (const float*)d_in[3];
    const float* W2 = (const float*)d_in[4];
    const float* b2 = (const float*)d_in[5];
    float* out = (float*)d_out;

    const size_t smem_bytes = SM_FLOATS * sizeof(float);  // 190464
    cudaFuncSetAttribute(sigma_persist_kernel,
                         cudaFuncAttributeMaxDynamicSharedMemorySize,
                         (int)smem_bytes);
    sigma_persist_kernel<<<GRID, NT, smem_bytes>>>(s, a, W1, b1, W2, b2, out);
}

// round 7
// speedup vs baseline: 2.3595x; 2.3595x over previous
#include <cuda_runtime.h>
#include <cstdint>

// SigmaModel, persistent-CTA + chunked coalesced epilogue.
// h = relu([s,a] @ W1^T + b1); tri = h @ W2^T + b2;
// out[b,i,j] = tri[t(min(i,j),max(i,j))], diag -> exp.
// 152 persistent CTAs; W2 staged once; tri buffer in 16-row chunks.

#define BATCH    131072
#define SDIM     32
#define ADIM     8
#define INDIM    40
#define HID      64
#define TRI      528
#define ROWS     64               // rows per tile
#define NT       512
#define GRID     152              // GB300 SM count
#define NTILES   (BATCH / ROWS)   // 2048
#define NPAD     580              // W2 k-major stride
#define TPAD     578              // tri chunk stride
#define HPAD     65               // H stride (banked rows)
#define XPAD     40               // X stride (16B-aligned cp.async rows)

// shared memory layout (float offsets)
#define SM_W2    0                // [64][NPAD] = 37120, persists
#define SM_TRI   37120            // [16][TPAD] = 9248 (epilogue chunk)
#define SM_H     46368            // [64][HPAD] = 4160
#define SM_X     50528            // [64][XPAD] = 2560
#define SM_W1    53088            // [40][64] transposed = 2560
#define SM_B1    55648            // [64]
#define SM_B2    55712            // [576]
#define SM_TBL   56288            // int[1024]
#define SM_FLOATS 57312           // 229248 bytes

typedef unsigned long long u64;

__device__ __forceinline__ u64 pack2(float lo, float hi) {
    u64 r; asm("mov.b64 %0, {%1, %2};" : "=l"(r) : "f"(lo), "f"(hi)); return r;
}
__device__ __forceinline__ void unpack2(u64 v, float& lo, float& hi) {
    asm("mov.b64 {%0, %1}, %2;" : "=f"(lo), "=f"(hi) : "l"(v));
}
__device__ __forceinline__ void fma2(u64& d, u64 a, u64 b) {
    asm("fma.rn.f32x2 %0, %1, %2, %0;" : "+l"(d) : "l"(a), "l"(b));
}
__device__ __forceinline__ uint32_t smem_u32(const void* p) {
    uint32_t r;
    asm("{ .reg .u64 t; cvta.to.shared.u64 t, %1; cvt.u32.u64 %0, t; }" : "=r"(r) : "l"(p));
    return r;
}
__device__ __forceinline__ void cp16(uint32_t dst, const void* src) {
    asm volatile("cp.async.ca.shared.global [%0], [%1], 16;" :: "r"(dst), "l"(src));
}
__device__ __forceinline__ void cp_commit() {
    asm volatile("cp.async.commit_group;" ::: "memory");
}
__device__ __forceinline__ void cp_wait0() {
    asm volatile("cp.async.wait_group 0;" ::: "memory");
}

__global__ void __launch_bounds__(NT, 1)
sigma_persist_kernel(const float* __restrict__ s,
                     const float* __restrict__ a,
                     const float* __restrict__ W1,
                     const float* __restrict__ b1,
                     const float* __restrict__ W2,
                     const float* __restrict__ b2,
                     float* __restrict__ out) {
    extern __shared__ float smem[];
    float* sW2  = smem + SM_W2;
    float* sTri = smem + SM_TRI;
    float* sH   = smem + SM_H;
    float* sX   = smem + SM_X;
    float* sW1  = smem + SM_W1;
    float* sB1  = smem + SM_B1;
    float* sB2  = smem + SM_B2;
    int*   sTbl = (int*)(smem + SM_TBL);

    const int tid = threadIdx.x;
    const uint32_t sXaddr = smem_u32(sX);

    // ================= one-time staging =================
    // W2[t][k] -> sW2[k][t] via LDG.128 along k (transpose STS, one-time)
    for (int idx = tid; idx < TRI * (HID / 4); idx += NT) {
        int t = idx >> 4, k4 = idx & 15;
        float4 w = *reinterpret_cast<const float4*>(&W2[t * HID + k4 * 4]);
        sW2[(4 * k4 + 0) * NPAD + t] = w.x;
        sW2[(4 * k4 + 1) * NPAD + t] = w.y;
        sW2[(4 * k4 + 2) * NPAD + t] = w.z;
        sW2[(4 * k4 + 3) * NPAD + t] = w.w;
    }
    // zero-pad W2 cols [TRI, NPAD)
    for (int idx = tid; idx < HID * (NPAD - TRI); idx += NT) {
        int k = idx / (NPAD - TRI), t = TRI + (idx - k * (NPAD - TRI));
        sW2[k * NPAD + t] = 0.0f;
    }
    // W1[hh][k] -> sW1[k][hh]
    for (int idx = tid; idx < HID * INDIM; idx += NT) {
        int hh = idx / INDIM, k = idx - hh * INDIM;
        sW1[k * HID + hh] = W1[idx];
    }
    if (tid < HID) sB1[tid] = b1[tid];
    for (int idx = tid; idx < 576; idx += NT)
        sB2[idx] = (idx < TRI) ? b2[idx] : 0.0f;
    // scatter table: out (i,j) -> tri index | diag flag
    for (int o = tid; o < 1024; o += NT) {
        int i = o >> 5, j = o & 31;
        int ii = (i < j) ? i : j;
        int jj = (i < j) ? j : i;
        int t = ii * 32 - ((ii * (ii + 1)) >> 1) + jj;
        sTbl[o] = t | ((i == j) ? (1 << 16) : 0);
    }

    // prefetch X for first tile
    const int tile0 = blockIdx.x;
    {
        int row0 = tile0 * ROWS;
        int r = tid >> 3, c4 = tid & 7;
        cp16(sXaddr + (r * XPAD + c4 * 4) * 4, &s[(size_t)(row0 + r) * SDIM + c4 * 4]);
        if (tid < 128) {
            int r2 = tid >> 1, d4 = tid & 1;
            cp16(sXaddr + (r2 * XPAD + SDIM + d4 * 4) * 4,
                 &a[(size_t)(row0 + r2) * ADIM + d4 * 4]);
        }
        cp_commit();
    }
    cp_wait0();
    __syncthreads();

    // GEMM thread mapping (constant across tiles)
    const int wi   = tid >> 5, lane = tid & 31;
    const int rb   = wi >> 3,  cb   = wi & 7;     // 2 row-blocks x 8 col-blocks
    const int rg   = lane & 7, cg   = lane >> 3;  // 8 row-groups x 4 col-groups
    const int wcol = cb * 72;
    const int4* tbl4 = reinterpret_cast<const int4*>(sTbl);

    // ================= persistent tile loop =================
    for (int tile = tile0; tile < NTILES; tile += GRID) {
        const int row0 = tile * ROWS;

        // ---- Phase 1: H = relu(X @ W1^T + b1) ----
        {
            const int r  = tid >> 3;
            const int hg = (tid & 7) * 8;
            u64 acc[4];
#pragma unroll
            for (int u = 0; u < 4; ++u)
                acc[u] = *reinterpret_cast<const u64*>(&sB1[hg + 2 * u]);
            const float* xrow = &sX[r * XPAD];
#pragma unroll 5
            for (int k = 0; k < INDIM; ++k) {
                u64 xb = pack2(xrow[k], xrow[k]);
                const ulonglong2 w0 = *reinterpret_cast<const ulonglong2*>(&sW1[k * HID + hg]);
                const ulonglong2 w1 = *reinterpret_cast<const ulonglong2*>(&sW1[k * HID + hg + 4]);
                fma2(acc[0], xb, w0.x); fma2(acc[1], xb, w0.y);
                fma2(acc[2], xb, w1.x); fma2(acc[3], xb, w1.y);
            }
            float* hrow = &sH[r * HPAD + hg];
#pragma unroll
            for (int u = 0; u < 4; ++u) {
                float lo, hi; unpack2(acc[u], lo, hi);
                hrow[2 * u]     = fmaxf(lo, 0.0f);
                hrow[2 * u + 1] = fmaxf(hi, 0.0f);
            }
        }
        __syncthreads();   // sH ready; sX free for prefetch

        // ---- prefetch X of next tile (hidden under GEMM) ----
        if (tile + GRID < NTILES) {
            int nrow0 = (tile + GRID) * ROWS;
            int r = tid >> 3, c4 = tid & 7;
            cp16(sXaddr + (r * XPAD + c4 * 4) * 4, &s[(size_t)(nrow0 + r) * SDIM + c4 * 4]);
            if (tid < 128) {
                int r2 = tid >> 1, d4 = tid & 1;
                cp16(sXaddr + (r2 * XPAD + SDIM + d4 * 4) * 4,
                     &a[(size_t)(nrow0 + r2) * ADIM + d4 * 4]);
            }
            cp_commit();
        }

        // ---- Phase 2: tri = H @ W2^T + b2 ----
        u64 acc2[4][9];
#pragma unroll
        for (int q = 0; q < 4; ++q) {
            u64 blo = *reinterpret_cast<const u64*>(&sB2[wcol + 16 * q + 4 * cg]);
            u64 bhi = *reinterpret_cast<const u64*>(&sB2[wcol + 16 * q + 4 * cg + 2]);
#pragma unroll
            for (int m = 0; m < 4; ++m) { acc2[m][2 * q] = blo; acc2[m][2 * q + 1] = bhi; }
        }
        {
            u64 bt = *reinterpret_cast<const u64*>(&sB2[wcol + 64 + 2 * cg]);
#pragma unroll
            for (int m = 0; m < 4; ++m) acc2[m][8] = bt;
        }

        const float* hbase = &sH[(rb * 32 + rg) * HPAD];
#pragma unroll 1
        for (int k = 0; k < HID; ++k) {
            const float* wr = &sW2[k * NPAD + wcol];
            const ulonglong2 q0 = *reinterpret_cast<const ulonglong2*>(wr + 4 * cg);
            const ulonglong2 q1 = *reinterpret_cast<const ulonglong2*>(wr + 16 + 4 * cg);
            const ulonglong2 q2 = *reinterpret_cast<const ulonglong2*>(wr + 32 + 4 * cg);
            const ulonglong2 q3 = *reinterpret_cast<const ulonglong2*>(wr + 48 + 4 * cg);
            const u64 qt = *reinterpret_cast<const u64*>(wr + 64 + 2 * cg);
            u64 hb[4];
#pragma unroll
            for (int m = 0; m < 4; ++m) {
                float hv = hbase[m * 8 * HPAD + k];
                hb[m] = pack2(hv, hv);
            }
#pragma unroll
            for (int m = 0; m < 4; ++m) {
                fma2(acc2[m][0], hb[m], q0.x);
                fma2(acc2[m][1], hb[m], q0.y);
                fma2(acc2[m][2], hb[m], q1.x);
                fma2(acc2[m][3], hb[m], q1.y);
                fma2(acc2[m][4], hb[m], q2.x);
                fma2(acc2[m][5], hb[m], q2.y);
                fma2(acc2[m][6], hb[m], q3.x);
                fma2(acc2[m][7], hb[m], q3.y);
                fma2(acc2[m][8], hb[m], qt);
            }
        }

        // ---- Phase 3: 4 chunked epilogue phases of 16 rows each ----
        // Thread rows: rb*32 + rg + 8m. Phase p covers rows [16p, 16p+16):
        // writers have rb == p>>1, m in {2*(p&1), 2*(p&1)+1}; chunk row = rg+8mm.
#pragma unroll
        for (int p = 0; p < 4; ++p) {
            if (rb == (p >> 1)) {
                const int mb = (p & 1) * 2;
#pragma unroll
                for (int mm = 0; mm < 2; ++mm) {
                    const int m = mb + mm;
                    float* trow = &sTri[(rg + 8 * mm) * TPAD + wcol];
#pragma unroll
                    for (int q = 0; q < 4; ++q) {
                        *reinterpret_cast<u64*>(trow + 16 * q + 4 * cg)     = acc2[m][2 * q];
                        *reinterpret_cast<u64*>(trow + 16 * q + 4 * cg + 2) = acc2[m][2 * q + 1];
                    }
                    *reinterpret_cast<u64*>(trow + 64 + 2 * cg) = acc2[m][8];
                }
            }
            __syncthreads();

            // coalesced scatter of 16 rows
            float4* out4 = reinterpret_cast<float4*>(out + (size_t)(row0 + p * 16) * 1024);
            for (int idx = tid; idx < 16 * 256; idx += NT) {
                const int r  = idx >> 8;
                const int o4 = idx & 255;
                const int4 tt = tbl4[o4];
                const float* tr = &sTri[r * TPAD];
                float v0 = tr[tt.x & 0xffff];
                float v1 = tr[tt.y & 0xffff];
                float v2 = tr[tt.z & 0xffff];
                float v3 = tr[tt.w & 0xffff];
                if (tt.x >> 16) v0 = __expf(v0);
                if (tt.y >> 16) v1 = __expf(v1);
                if (tt.z >> 16) v2 = __expf(v2);
                if (tt.w >> 16) v3 = __expf(v3);
                out4[idx] = make_float4(v0, v1, v2, v3);
            }
            __syncthreads();
        }

        cp_wait0();   // X(t+1) landed; sH reads finished at GEMM end
    }
}

extern "C" void kernel_launch(void* const* d_in, const int* in_sizes, int n_in,
                              void* d_out, int out_size) {
    (void)in_sizes; (void)n_in; (void)out_size;
    const float* s  = (const float*)d_in[0];
    const float* a  = (const float*)d_in[1];
    const float* W1 = (const float*)d_in[2];
    const float* b1 = (const float*)d_in[3];
    const float* W2 = (const float*)d_in[4];
    const float* b2 = (const float*)d_in[5];
    float* out = (float*)d_out;

    const size_t smem_bytes = SM_FLOATS * sizeof(float);  // 229248
    cudaFuncSetAttribute(sigma_persist_kernel,
                         cudaFuncAttributeMaxDynamicSharedMemorySize,
                         (int)smem_bytes);
    sigma_persist_kernel<<<GRID, NT, smem_bytes>>>(s, a, W1, b1, W2, b2, out);
}

// round 8
// speedup vs baseline: 2.6847x; 1.1378x over previous
#include <cuda_runtime.h>
#include <cstdint>

// SigmaModel, persistent-CTA, 1024 threads (occ 50%), chunked coalesced epilogue.
// h = relu([s,a] @ W1^T + b1); tri = h @ W2^T + b2;
// out[b,i,j] = tri[t(min(i,j),max(i,j))], diag -> exp.
// 152 persistent CTAs; W2 staged once; thread tile 2r x 18c (36 acc regs).

#define BATCH    131072
#define SDIM     32
#define ADIM     8
#define INDIM    40
#define HID      64
#define TRI      528
#define ROWS     64               // rows per tile
#define NT       1024
#define GRID     152              // GB300 SM count
#define NTILES   (BATCH / ROWS)   // 2048
#define NPAD     580              // W2 k-major stride
#define TPAD     578              // tri chunk stride
#define HPAD     65               // H stride (banked rows)
#define XPAD     40               // X stride (16B-aligned cp.async rows)

// shared memory layout (float offsets)
#define SM_W2    0                // [64][NPAD] = 37120, persists
#define SM_TRI   37120            // [16][TPAD] = 9248 (epilogue chunk)
#define SM_H     46368            // [64][HPAD] = 4160
#define SM_X     50528            // [64][XPAD] = 2560
#define SM_W1    53088            // [40][64] transposed = 2560
#define SM_B1    55648            // [64]
#define SM_B2    55712            // [576]
#define SM_TBL   56288            // int[1024]
#define SM_FLOATS 57312           // 229248 bytes

typedef unsigned long long u64;

__device__ __forceinline__ u64 pack2(float lo, float hi) {
    u64 r; asm("mov.b64 %0, {%1, %2};" : "=l"(r) : "f"(lo), "f"(hi)); return r;
}
__device__ __forceinline__ void unpack2(u64 v, float& lo, float& hi) {
    asm("mov.b64 {%0, %1}, %2;" : "=f"(lo), "=f"(hi) : "l"(v));
}
__device__ __forceinline__ void fma2(u64& d, u64 a, u64 b) {
    asm("fma.rn.f32x2 %0, %1, %2, %0;" : "+l"(d) : "l"(a), "l"(b));
}
__device__ __forceinline__ uint32_t smem_u32(const void* p) {
    uint32_t r;
    asm("{ .reg .u64 t; cvta.to.shared.u64 t, %1; cvt.u32.u64 %0, t; }" : "=r"(r) : "l"(p));
    return r;
}
__device__ __forceinline__ void cp16(uint32_t dst, const void* src) {
    asm volatile("cp.async.ca.shared.global [%0], [%1], 16;" :: "r"(dst), "l"(src));
}
__device__ __forceinline__ void cp_commit() {
    asm volatile("cp.async.commit_group;" ::: "memory");
}
__device__ __forceinline__ void cp_wait0() {
    asm volatile("cp.async.wait_group 0;" ::: "memory");
}

__global__ void __launch_bounds__(NT, 1)
sigma_persist_kernel(const float* __restrict__ s,
                     const float* __restrict__ a,
                     const float* __restrict__ W1,
                     const float* __restrict__ b1,
                     const float* __restrict__ W2,
                     const float* __restrict__ b2,
                     float* __restrict__ out) {
    extern __shared__ float smem[];
    float* sW2  = smem + SM_W2;
    float* sTri = smem + SM_TRI;
    float* sH   = smem + SM_H;
    float* sX   = smem + SM_X;
    float* sW1  = smem + SM_W1;
    float* sB1  = smem + SM_B1;
    float* sB2  = smem + SM_B2;
    int*   sTbl = (int*)(smem + SM_TBL);

    const int tid = threadIdx.x;
    const uint32_t sXaddr = smem_u32(sX);

    // ================= one-time staging =================
    // W2[t][k] -> sW2[k][t] via LDG.128 along k
    for (int idx = tid; idx < TRI * (HID / 4); idx += NT) {
        int t = idx >> 4, k4 = idx & 15;
        float4 w = *reinterpret_cast<const float4*>(&W2[t * HID + k4 * 4]);
        sW2[(4 * k4 + 0) * NPAD + t] = w.x;
        sW2[(4 * k4 + 1) * NPAD + t] = w.y;
        sW2[(4 * k4 + 2) * NPAD + t] = w.z;
        sW2[(4 * k4 + 3) * NPAD + t] = w.w;
    }
    // zero-pad W2 cols [TRI, NPAD)
    for (int idx = tid; idx < HID * (NPAD - TRI); idx += NT) {
        int k = idx / (NPAD - TRI), t = TRI + (idx - k * (NPAD - TRI));
        sW2[k * NPAD + t] = 0.0f;
    }
    // W1[hh][k] -> sW1[k][hh]
    for (int idx = tid; idx < HID * INDIM; idx += NT) {
        int hh = idx / INDIM, k = idx - hh * INDIM;
        sW1[k * HID + hh] = W1[idx];
    }
    if (tid < HID) sB1[tid] = b1[tid];
    for (int idx = tid; idx < 576; idx += NT)
        sB2[idx] = (idx < TRI) ? b2[idx] : 0.0f;
    // scatter table: out (i,j) -> tri index | diag flag
    for (int o = tid; o < 1024; o += NT) {
        int i = o >> 5, j = o & 31;
        int ii = (i < j) ? i : j;
        int jj = (i < j) ? j : i;
        int t = ii * 32 - ((ii * (ii + 1)) >> 1) + jj;
        sTbl[o] = t | ((i == j) ? (1 << 16) : 0);
    }

    // prefetch X for first tile
    const int tile0 = blockIdx.x;
    {
        int row0 = tile0 * ROWS;
        if (tid < 512) {
            int r = tid >> 3, c4 = tid & 7;
            cp16(sXaddr + (r * XPAD + c4 * 4) * 4, &s[(size_t)(row0 + r) * SDIM + c4 * 4]);
        } else if (tid < 640) {
            int t2 = tid - 512, r2 = t2 >> 1, d4 = t2 & 1;
            cp16(sXaddr + (r2 * XPAD + SDIM + d4 * 4) * 4,
                 &a[(size_t)(row0 + r2) * ADIM + d4 * 4]);
        }
        cp_commit();
    }
    cp_wait0();
    __syncthreads();

    // GEMM thread mapping: 32 warps = 4 row-blocks(16r) x 8 col-blocks(72c).
    const int wi   = tid >> 5, lane = tid & 31;
    const int rb   = wi >> 3,  cb   = wi & 7;
    const int rg   = lane & 7, cg   = lane >> 3;
    const int wcol = cb * 72;
    const int4* tbl4 = reinterpret_cast<const int4*>(sTbl);

    // ================= persistent tile loop =================
    for (int tile = tile0; tile < NTILES; tile += GRID) {
        const int row0 = tile * ROWS;

        // ---- Phase 1: H = relu(X @ W1^T + b1) ----
        {
            const int r  = tid >> 4;           // 0..63
            const int hg = (tid & 15) * 4;     // 4 hidden cols = 2 pairs
            u64 acc[2];
            acc[0] = *reinterpret_cast<const u64*>(&sB1[hg]);
            acc[1] = *reinterpret_cast<const u64*>(&sB1[hg + 2]);
            const float* xrow = &sX[r * XPAD];
#pragma unroll 5
            for (int k = 0; k < INDIM; ++k) {
                u64 xb = pack2(xrow[k], xrow[k]);
                const ulonglong2 w = *reinterpret_cast<const ulonglong2*>(&sW1[k * HID + hg]);
                fma2(acc[0], xb, w.x);
                fma2(acc[1], xb, w.y);
            }
            float* hrow = &sH[r * HPAD + hg];
            float l0, h0, l1, h1;
            unpack2(acc[0], l0, h0);
            unpack2(acc[1], l1, h1);
            hrow[0] = fmaxf(l0, 0.0f);
            hrow[1] = fmaxf(h0, 0.0f);
            hrow[2] = fmaxf(l1, 0.0f);
            hrow[3] = fmaxf(h1, 0.0f);
        }
        __syncthreads();   // sH ready; sX free for prefetch

        // ---- prefetch X of next tile (hidden under GEMM) ----
        if (tile + GRID < NTILES) {
            int nrow0 = (tile + GRID) * ROWS;
            if (tid < 512) {
                int r = tid >> 3, c4 = tid & 7;
                cp16(sXaddr + (r * XPAD + c4 * 4) * 4,
                     &s[(size_t)(nrow0 + r) * SDIM + c4 * 4]);
            } else if (tid < 640) {
                int t2 = tid - 512, r2 = t2 >> 1, d4 = t2 & 1;
                cp16(sXaddr + (r2 * XPAD + SDIM + d4 * 4) * 4,
                     &a[(size_t)(nrow0 + r2) * ADIM + d4 * 4]);
            }
            cp_commit();
        }

        // ---- Phase 2: tri = H @ W2^T + b2 (thread tile 2r x 18c) ----
        u64 acc2[2][9];
#pragma unroll
        for (int q = 0; q < 4; ++q) {
            u64 blo = *reinterpret_cast<const u64*>(&sB2[wcol + 16 * q + 4 * cg]);
            u64 bhi = *reinterpret_cast<const u64*>(&sB2[wcol + 16 * q + 4 * cg + 2]);
            acc2[0][2 * q] = blo; acc2[0][2 * q + 1] = bhi;
            acc2[1][2 * q] = blo; acc2[1][2 * q + 1] = bhi;
        }
        {
            u64 bt = *reinterpret_cast<const u64*>(&sB2[wcol + 64 + 2 * cg]);
            acc2[0][8] = bt; acc2[1][8] = bt;
        }

        const float* hbase = &sH[(rb * 16 + rg) * HPAD];
#pragma unroll 1
        for (int k = 0; k < HID; ++k) {
            u64 hb0, hb1;
            {
                float h0 = hbase[k];
                float h1 = hbase[8 * HPAD + k];
                hb0 = pack2(h0, h0);
                hb1 = pack2(h1, h1);
            }
            const float* wr = &sW2[k * NPAD + wcol];
#pragma unroll
            for (int q = 0; q < 4; ++q) {
                const ulonglong2 w = *reinterpret_cast<const ulonglong2*>(wr + 16 * q + 4 * cg);
                fma2(acc2[0][2 * q],     hb0, w.x);
                fma2(acc2[0][2 * q + 1], hb0, w.y);
                fma2(acc2[1][2 * q],     hb1, w.x);
                fma2(acc2[1][2 * q + 1], hb1, w.y);
            }
            {
                const u64 wt = *reinterpret_cast<const u64*>(wr + 64 + 2 * cg);
                fma2(acc2[0][8], hb0, wt);
                fma2(acc2[1][8], hb1, wt);
            }
        }

        // ---- Phase 3: 4 chunked epilogue phases of 16 rows each ----
        // Thread rows: rb*16 + rg + 8m (m=0,1). Phase p covers rows [16p,16p+16):
        // writers are warps with rb == p; chunk row = rg + 8m.
#pragma unroll
        for (int p = 0; p < 4; ++p) {
            if (rb == p) {
#pragma unroll
                for (int m = 0; m < 2; ++m) {
                    float* trow = &sTri[(rg + 8 * m) * TPAD + wcol];
#pragma unroll
                    for (int q = 0; q < 4; ++q) {
                        *reinterpret_cast<u64*>(trow + 16 * q + 4 * cg)     = acc2[m][2 * q];
                        *reinterpret_cast<u64*>(trow + 16 * q + 4 * cg + 2) = acc2[m][2 * q + 1];
                    }
                    *reinterpret_cast<u64*>(trow + 64 + 2 * cg) = acc2[m][8];
                }
            }
            __syncthreads();

            // coalesced scatter of 16 rows (4 quads per thread)
            float4* out4 = reinterpret_cast<float4*>(out + (size_t)(row0 + p * 16) * 1024);
#pragma unroll
            for (int it = 0; it < 4; ++it) {
                const int idx = tid + it * NT;
                const int r  = idx >> 8;
                const int o4 = idx & 255;
                const int4 tt = tbl4[o4];
                const float* tr = &sTri[r * TPAD];
                float v0 = tr[tt.x & 0xffff];
                float v1 = tr[tt.y & 0xffff];
                float v2 = tr[tt.z & 0xffff];
                float v3 = tr[tt.w & 0xffff];
                if (tt.x >> 16) v0 = __expf(v0);
                if (tt.y >> 16) v1 = __expf(v1);
                if (tt.z >> 16) v2 = __expf(v2);
                if (tt.w >> 16) v3 = __expf(v3);
                out4[idx] = make_float4(v0, v1, v2, v3);
            }
            if (p == 3) cp_wait0();   // X(t+1) landed before the barrier below
            __syncthreads();
        }
    }
}

extern "C" void kernel_launch(void* const* d_in, const int* in_sizes, int n_in,
                              void* d_out, int out_size) {
    (void)in_sizes; (void)n_in; (void)out_size;
    const float* s  = (const float*)d_in[0];
    const float* a  = (const float*)d_in[1];
    const float* W1 = (const float*)d_in[2];
    const float* b1 = (const float*)d_in[3];
    const float* W2 = (const float*)d_in[4];
    const float* b2 = (const float*)d_in[5];
    float* out = (float*)d_out;

    const size_t smem_bytes = SM_FLOATS * sizeof(float);  // 229248
    cudaFuncSetAttribute(sigma_persist_kernel,
                         cudaFuncAttributeMaxDynamicSharedMemorySize,
                         (int)smem_bytes);
    sigma_persist_kernel<<<GRID, NT, smem_bytes>>>(s, a, W1, b1, W2, b2, out);
}